// round 6
// baseline (speedup 1.0000x reference)
#include <cuda_runtime.h>

// EMA with bias correction — multi-row CTA with register double-buffer prefetch.
// x: (32, 256, 8192) f32 -> 8192 rows of T=8192.
// y[t] = 0.99*y[t-1] + 0.01*x[t];  out[t] = y[t] / (1 - 0.99^(t+1))
//
// Block = 512 thr (16 warps) processes ROWS_PER_CTA=4 consecutive rows.
// Within a row: warp w owns [w*512, (w+1)*512); lane l holds 4 groups of 4
// contiguous floats at i*128 + l*4 -> all LDG.128/STG.128 warp-coalesced.
// Row r+1's loads are issued BEFORE row r's scan/sync/store phase (ping-pong
// register buffers), keeping the DRAM read stream continuous.
//
// Bias correction: t >= 2048 -> 0.99^(t+1) < 2^-25, fp32 corr == 1.0 exactly
// (warps 4..15 skip). Warps 0-3 compute corr inline (exact constant products
// + MUFU reciprocal, hidden under memory).

#define T_LEN   8192
#define THREADS 512
#define NWARP   (THREADS / 32)    // 16
#define SEG     (T_LEN / NWARP)   // 512 elems per warp
#define NBLK    (SEG / 128)       // 4 blocks of 128 per warp
#define ROWS_PER_CTA 4

#define OM 0.99f
#define MM 0.01f

// Compile-time decay constants
#define A4_1  (OM*OM*OM*OM)       // 0.99^4
#define A4_2  (A4_1*A4_1)         // 0.99^8
#define A4_4  (A4_2*A4_2)         // 0.99^16
#define A4_8  (A4_4*A4_4)         // 0.99^32
#define A4_16 (A4_8*A4_8)         // 0.99^64
#define A128  (A4_16*A4_16)       // 0.99^128
#define A512  (A128*A128*A128*A128) // 0.99^512

// Per-block serial affine + b-only warp Kogge-Stone (lane decay uniform A4).
__device__ __forceinline__ void scan_row(const float4 v[NBLK],
                                         float excl[NBLK], float b128[NBLK],
                                         int lane) {
#pragma unroll
    for (int i = 0; i < NBLK; i++) {
        float b;
        b = MM * v[i].x;
        b = fmaf(OM, b, MM * v[i].y);
        b = fmaf(OM, b, MM * v[i].z);
        b = fmaf(OM, b, MM * v[i].w);

        float t1 = __shfl_up_sync(0xffffffffu, b, 1);
        if (lane >= 1)  b = fmaf(A4_1,  t1, b);
        float t2 = __shfl_up_sync(0xffffffffu, b, 2);
        if (lane >= 2)  b = fmaf(A4_2,  t2, b);
        float t4 = __shfl_up_sync(0xffffffffu, b, 4);
        if (lane >= 4)  b = fmaf(A4_4,  t4, b);
        float t8 = __shfl_up_sync(0xffffffffu, b, 8);
        if (lane >= 8)  b = fmaf(A4_8,  t8, b);
        float t16 = __shfl_up_sync(0xffffffffu, b, 16);
        if (lane >= 16) b = fmaf(A4_16, t16, b);

        float e = __shfl_up_sync(0xffffffffu, b, 1);
        excl[i] = (lane == 0) ? 0.0f : e;          // carry into lane l, block i
        b128[i] = __shfl_sync(0xffffffffu, b, 31); // block-i total
    }
}

__global__ __launch_bounds__(THREADS, 2)
void ema_kernel(const float* __restrict__ x, float* __restrict__ out) {
    const int lane = threadIdx.x & 31;
    const int warp = threadIdx.x >> 5;

    __shared__ float wsum[2][NWARP];

    // Lane decay 0.99^(4*lane) via binary products of constants
    float al = (lane & 1) ? A4_1 : 1.0f;
    if (lane & 2)  al *= A4_2;
    if (lane & 4)  al *= A4_4;
    if (lane & 8)  al *= A4_8;
    if (lane & 16) al *= A4_16;

    // q = 0.99^(t+1) at this lane's first element (same for every row);
    // only meaningful for warp < 4.
    float qb0 = OM * al;
    if (warp & 1) qb0 *= A512;
    if (warp & 2) qb0 *= A512 * A512;

    const size_t base = (size_t)blockIdx.x * (ROWS_PER_CTA * T_LEN)
                      + (size_t)warp * SEG + (size_t)lane * 4;
    const float4* __restrict__ p  = (const float4*)(x   + base);
    float4*       __restrict__ po = (float4*)      (out + base);

    float4 va[NBLK], vb[NBLK];

    // Prefetch row 0
#pragma unroll
    for (int i = 0; i < NBLK; i++) va[i] = __ldcs(p + i * 32);

#pragma unroll
    for (int r = 0; r < ROWS_PER_CTA; r++) {
        const float4* v  = (r & 1) ? vb : va;
        float4*       vn = (r & 1) ? va : vb;

        // Prefetch next row before this row's compute/sync/store phase
        if (r + 1 < ROWS_PER_CTA) {
            const float4* pn = p + (size_t)(r + 1) * (T_LEN / 4);
#pragma unroll
            for (int i = 0; i < NBLK; i++) vn[i] = __ldcs(pn + i * 32);
        }

        float excl[NBLK], b128[NBLK];
        scan_row(v, excl, b128, lane);

        // Warp total over its 512 elements
        float tot = b128[0];
#pragma unroll
        for (int i = 1; i < NBLK; i++) tot = fmaf(A128, tot, b128[i]);

        if (lane == 0) wsum[r & 1][warp] = tot;
        __syncthreads();

        // Carry into this warp: ordered combine of prior warp totals
        float cw = 0.0f;
#pragma unroll
        for (int j = 0; j < NWARP; j++) {
            if (j < warp) cw = fmaf(A512, cw, wsum[r & 1][j]);
        }

        float4* pr = po + (size_t)r * (T_LEN / 4);

        if (warp < 4) {
            // t = warp*512 + i*128 + lane*4 + j < 2048: apply correction
            float qb = qb0;
            float c = cw;
#pragma unroll
            for (int i = 0; i < NBLK; i++) {
                float cc = fmaf(al, c, excl[i]);
                float q = qb;
                float4 w;
                cc = fmaf(OM, cc, MM * v[i].x); w.x = __fdividef(cc, 1.0f - q); q *= OM;
                cc = fmaf(OM, cc, MM * v[i].y); w.y = __fdividef(cc, 1.0f - q); q *= OM;
                cc = fmaf(OM, cc, MM * v[i].z); w.z = __fdividef(cc, 1.0f - q); q *= OM;
                cc = fmaf(OM, cc, MM * v[i].w); w.w = __fdividef(cc, 1.0f - q);
                __stcs(pr + i * 32, w);
                c  = fmaf(A128, c, b128[i]);
                qb *= A128;
            }
        } else {
            // t >= 2048: corr == 1.0f exactly in fp32
            float c = cw;
#pragma unroll
            for (int i = 0; i < NBLK; i++) {
                float cc = fmaf(al, c, excl[i]);
                float4 w;
                cc = fmaf(OM, cc, MM * v[i].x); w.x = cc;
                cc = fmaf(OM, cc, MM * v[i].y); w.y = cc;
                cc = fmaf(OM, cc, MM * v[i].z); w.z = cc;
                cc = fmaf(OM, cc, MM * v[i].w); w.w = cc;
                __stcs(pr + i * 32, w);
                c = fmaf(A128, c, b128[i]);
            }
        }
    }
}

extern "C" void kernel_launch(void* const* d_in, const int* in_sizes, int n_in,
                              void* d_out, int out_size) {
    const float* x = (const float*)d_in[0];
    float* out = (float*)d_out;

    int rows = in_sizes[0] / T_LEN;            // 8192
    int blocks = rows / ROWS_PER_CTA;          // 2048

    ema_kernel<<<blocks, THREADS>>>(x, out);
}

// round 7
// speedup vs baseline: 1.0125x; 1.0125x over previous
#include <cuda_runtime.h>

// EMA with bias correction — 512-thread CTA, 2 rows/CTA, R3-style warp shape.
// x: (32, 256, 8192) f32 -> 8192 rows of T=8192.
// y[t] = 0.99*y[t-1] + 0.01*x[t];  out[t] = y[t] / (1 - 0.99^(t+1))
//
// CTA = 16 warps: warps 0-7 own row A, warps 8-15 own row B. Within a row,
// sub-warp sw owns [sw*1024, (sw+1)*1024); lane l holds 8 groups of 4
// contiguous floats at i*128 + l*4 -> all LDG.128/STG.128 warp-coalesced,
// 8 loads front-batched per thread (MLP_p1 = 8). One __syncthreads serves
// the cross-warp carry exchange of both rows.
//
// Bias correction: t >= 2048 -> 0.99^(t+1) < 2^-25, fp32 corr == 1.0 exactly
// (sub-warps 2..7 skip). Sub-warps 0-1 compute corr inline from exact
// constant products + MUFU reciprocal (hidden under memory latency).

#define T_LEN   8192
#define THREADS 512
#define NWARP   16
#define ROWS_PER_CTA 2
#define NBLK    8                 // 8 blocks of 128 per warp (SEG = 1024)

#define OM 0.99f
#define MM 0.01f

#define A4_1  (OM*OM*OM*OM)       // 0.99^4
#define A4_2  (A4_1*A4_1)         // 0.99^8
#define A4_4  (A4_2*A4_2)         // 0.99^16
#define A4_8  (A4_4*A4_4)         // 0.99^32
#define A4_16 (A4_8*A4_8)         // 0.99^64
#define A128  (A4_16*A4_16)       // 0.99^128
#define A1024 (A128*A128*A128*A128*A128*A128*A128*A128)  // 0.99^1024

__global__ __launch_bounds__(THREADS, 2)
void ema_kernel(const float* __restrict__ x, float* __restrict__ out) {
    const int lane = threadIdx.x & 31;
    const int warp = threadIdx.x >> 5;
    const int r    = warp >> 3;        // 0/1: which row in this CTA
    const int sw   = warp & 7;         // sub-warp index within the row

    __shared__ float wsum[NWARP];

    // Lane decay 0.99^(4*lane) via binary products of constants
    float al = (lane & 1) ? A4_1 : 1.0f;
    if (lane & 2)  al *= A4_2;
    if (lane & 4)  al *= A4_4;
    if (lane & 8)  al *= A4_8;
    if (lane & 16) al *= A4_16;

    const size_t base = (size_t)(blockIdx.x * ROWS_PER_CTA + r) * T_LEN
                      + (size_t)sw * 1024 + (size_t)lane * 4;
    const float4* __restrict__ p  = (const float4*)(x   + base);
    float4*       __restrict__ po = (float4*)      (out + base);

    // Front-batched coalesced streaming loads: block i at +i*128 floats
    float4 v[NBLK];
#pragma unroll
    for (int i = 0; i < NBLK; i++) v[i] = __ldcs(p + i * 32);

    // Per-block serial affine over 4 elems, then b-only warp Kogge-Stone
    // (decay per lane is uniform A4, so only b scans).
    float excl[NBLK], b128[NBLK];
#pragma unroll
    for (int i = 0; i < NBLK; i++) {
        float b;
        b = MM * v[i].x;
        b = fmaf(OM, b, MM * v[i].y);
        b = fmaf(OM, b, MM * v[i].z);
        b = fmaf(OM, b, MM * v[i].w);

        float t1 = __shfl_up_sync(0xffffffffu, b, 1);
        if (lane >= 1)  b = fmaf(A4_1,  t1, b);
        float t2 = __shfl_up_sync(0xffffffffu, b, 2);
        if (lane >= 2)  b = fmaf(A4_2,  t2, b);
        float t4 = __shfl_up_sync(0xffffffffu, b, 4);
        if (lane >= 4)  b = fmaf(A4_4,  t4, b);
        float t8 = __shfl_up_sync(0xffffffffu, b, 8);
        if (lane >= 8)  b = fmaf(A4_8,  t8, b);
        float t16 = __shfl_up_sync(0xffffffffu, b, 16);
        if (lane >= 16) b = fmaf(A4_16, t16, b);

        float e = __shfl_up_sync(0xffffffffu, b, 1);
        excl[i] = (lane == 0) ? 0.0f : e;          // carry into lane l, block i
        b128[i] = __shfl_sync(0xffffffffu, b, 31); // block-i total
    }

    // Warp total over its 1024 elements: chain the 8 block totals
    float tot = b128[0];
#pragma unroll
    for (int i = 1; i < NBLK; i++) tot = fmaf(A128, tot, b128[i]);

    if (lane == 0) wsum[warp] = tot;
    __syncthreads();

    // Carry into this warp: ordered combine of prior sub-warps of OWN row
    float cw = 0.0f;
#pragma unroll
    for (int jj = 0; jj < 8; jj++) {
        if (jj < sw) cw = fmaf(A1024, cw, wsum[(r << 3) + jj]);
    }

    if (sw < 2) {
        // t = sw*1024 + i*128 + lane*4 + j < 2048: apply correction.
        // q at this lane's (i=0, j=0) element: 0.99^(sw*1024 + lane*4 + 1)
        float qb = OM * al;
        if (sw == 1) qb *= A1024;

        float c = cw;  // EMA state at block-i start (lane 0 position)
#pragma unroll
        for (int i = 0; i < NBLK; i++) {
            float cc = fmaf(al, c, excl[i]);   // carry into this lane's group
            float q = qb;
            float4 w;
            cc = fmaf(OM, cc, MM * v[i].x); w.x = __fdividef(cc, 1.0f - q); q *= OM;
            cc = fmaf(OM, cc, MM * v[i].y); w.y = __fdividef(cc, 1.0f - q); q *= OM;
            cc = fmaf(OM, cc, MM * v[i].z); w.z = __fdividef(cc, 1.0f - q); q *= OM;
            cc = fmaf(OM, cc, MM * v[i].w); w.w = __fdividef(cc, 1.0f - q);
            __stcs(po + i * 32, w);
            c  = fmaf(A128, c, b128[i]);       // state at next block start
            qb *= A128;
        }
    } else {
        // t >= 2048: 0.99^(t+1) < 2^-25 -> fp32 corr == 1.0 exactly
        float c = cw;
#pragma unroll
        for (int i = 0; i < NBLK; i++) {
            float cc = fmaf(al, c, excl[i]);
            float4 w;
            cc = fmaf(OM, cc, MM * v[i].x); w.x = cc;
            cc = fmaf(OM, cc, MM * v[i].y); w.y = cc;
            cc = fmaf(OM, cc, MM * v[i].z); w.z = cc;
            cc = fmaf(OM, cc, MM * v[i].w); w.w = cc;
            __stcs(po + i * 32, w);
            c = fmaf(A128, c, b128[i]);
        }
    }
}

extern "C" void kernel_launch(void* const* d_in, const int* in_sizes, int n_in,
                              void* d_out, int out_size) {
    const float* x = (const float*)d_in[0];
    float* out = (float*)d_out;

    int rows = in_sizes[0] / T_LEN;        // 8192
    int blocks = rows / ROWS_PER_CTA;      // 4096

    ema_kernel<<<blocks, THREADS>>>(x, out);
}